// round 8
// baseline (speedup 1.0000x reference)
#include <cuda_runtime.h>
#include <cstdint>
#include <cstddef>

// Problem constants (fixed shapes for this bench)
#define RON_DT 0.042f
static constexpr int Bx = 128;   // batch
static constexpr int Tx = 1024;  // timesteps
static constexpr int Ix = 64;    // input dim
static constexpr int Hx = 512;   // hidden dim
static constexpr int NTHREADS = 512;

// Cluster partitioning: 16 clusters x 8 CTAs. Each cluster owns 8 batches,
// each CTA owns 64 j-columns. h2h weights live in REGISTERS (64/thread).
// Cross-CTA hy exchange: st.async + transaction-counting mbarriers (no
// full cluster barrier in the hot loop).
static constexpr int CLUSTER_SZ = 8;
static constexpr int JPC = 64;   // j columns per CTA
static constexpr int BPC = 8;    // batches per cluster

// SMEM layout (float offsets)
static constexpr int OFF_X2H = 0;          // [64][64]   x2h column slice
static constexpr int OFF_HY0 = 4096;       // [512][8]   hy mirror, phase 0 (k-major, b fastest)
static constexpr int OFF_HY1 = 8192;       // [512][8]   hy mirror, phase 1
static constexpr int OFF_XS0 = 12288;      // [64][8]    x staging, phase 0
static constexpr int OFF_XS1 = 12800;      // [64][8]    x staging, phase 1
static constexpr int OFF_RED = 13312;      // [16][8*68] cross-warp reduction (pad 68)
static constexpr int RSTRIDE = 8 * 68;     // 544 floats per warp row
static constexpr int OFF_BAR = OFF_RED + 16 * RSTRIDE;   // 22016: two u64 mbarriers
static constexpr int SMEM_FLOATS = OFF_BAR + 8;
static constexpr size_t SMEM_BYTES = (size_t)SMEM_FLOATS * 4;  // 88096 B

// expect_tx per step: 8 ranks x 512 floats (hy) + 512 floats (own x staging)
static constexpr unsigned TX_BYTES = 8u * 512u * 4u + 512u * 4u;  // 18432

__device__ __forceinline__ uint32_t smem_u32(const void* p) {
    return (uint32_t)__cvta_generic_to_shared(p);
}

__device__ __forceinline__ uint64_t pack2(float lo, float hi) {
    uint64_t d;
    asm("mov.b64 %0, {%1, %2};" : "=l"(d) : "f"(lo), "f"(hi));
    return d;
}

__device__ __forceinline__ uint64_t fma2(uint64_t a, uint64_t b, uint64_t c) {
    uint64_t d;
    asm("fma.rn.f32x2 %0, %1, %2, %3;" : "=l"(d) : "l"(a), "l"(b), "l"(c));
    return d;
}

// 8 packed FMA2 = 16 scalar FMAs: batch-pairs h01..h67 x packed-splat weights wxx/wyy
__device__ __forceinline__ void accp16(uint64_t (&acc)[4][2], uint64_t wxx, uint64_t wyy,
                                       uint64_t h01, uint64_t h23, uint64_t h45, uint64_t h67) {
    acc[0][0] = fma2(h01, wxx, acc[0][0]); acc[0][1] = fma2(h01, wyy, acc[0][1]);
    acc[1][0] = fma2(h23, wxx, acc[1][0]); acc[1][1] = fma2(h23, wyy, acc[1][1]);
    acc[2][0] = fma2(h45, wxx, acc[2][0]); acc[2][1] = fma2(h45, wyy, acc[2][1]);
    acc[3][0] = fma2(h67, wxx, acc[3][0]); acc[3][1] = fma2(h67, wyy, acc[3][1]);
}

__device__ __forceinline__ void st_async_f32(uint32_t addr, float val, uint32_t mbar) {
    asm volatile("st.async.shared::cluster.mbarrier::complete_tx::bytes.b32 [%0], %1, [%2];"
                 :: "r"(addr), "r"(__float_as_uint(val)), "r"(mbar) : "memory");
}

extern __shared__ float smem[];

__global__ void __cluster_dims__(CLUSTER_SZ, 1, 1) __launch_bounds__(NTHREADS, 1)
ron_cluster_kernel(const float* __restrict__ x,
                   const float* __restrict__ x2h,
                   const float* __restrict__ h2h,
                   const float* __restrict__ bias,
                   const float* __restrict__ gamma,
                   const float* __restrict__ eps,
                   float* __restrict__ out_states,
                   float* __restrict__ out_hy,
                   int write_hy)
{
    const int tid  = threadIdx.x;
    const int w    = tid >> 5;     // warp 0..15 -> k-slice
    const int lane = tid & 31;

    uint32_t rank_u;
    asm("mov.u32 %0, %%cluster_ctarank;" : "=r"(rank_u));
    const int r     = (int)rank_u;            // j-slice owner within cluster
    const int cl    = blockIdx.x >> 3;        // cluster id
    const int b0    = cl * BPC;               // first global batch of this cluster
    const int jbase = r * JPC;                // first global j of this CTA

    const int k0  = w * 32;    // this warp's k slice (recurrent matvec)
    const int i0  = w * 4;     // this warp's i slice (input projection)
    const int jj0 = lane * 2;  // this lane's j pair

    // ---- Prologue ----
    // h2h weights into REGISTERS: thread holds w[kk] = (h2h[k0+kk][jbase+jj0], ...+1)
    float2 wreg[32];
    {
        const float2* src = reinterpret_cast<const float2*>(h2h + (size_t)k0 * Hx + jbase + jj0);
        #pragma unroll
        for (int kk = 0; kk < 32; ++kk)
            wreg[kk] = __ldg(src + (size_t)kk * (Hx / 2));
    }
    // x2h slice into SMEM: [64][64]
    #pragma unroll
    for (int it = 0; it < (Ix * JPC) / NTHREADS; ++it) {
        int idx = it * NTHREADS + tid;
        int i = idx >> 6, jj = idx & 63;
        smem[OFF_X2H + idx] = x2h[(size_t)i * Hx + jbase + jj];
    }
    // zero hy mirror phase 0 (initial hidden state)
    #pragma unroll
    for (int it = 0; it < (Hx * BPC) / NTHREADS; ++it)
        smem[OFF_HY0 + it * NTHREADS + tid] = 0.0f;

    // stage x for t=0 into xs phase 0: layout xs[i][b]
    const int pf_b = tid >> 6, pf_i = tid & 63;
    const float* xsrc_base = x + (size_t)(b0 + pf_b) * Tx * Ix + pf_i;
    smem[OFF_XS0 + pf_i * 8 + pf_b] = xsrc_base[0];

    // Update ownership: thread tid owns (column ojj = tid>>3, batch ob = tid&7)
    // so the mirror index (jbase+ojj)*8+ob == jbase*8 + tid (lane-consecutive).
    const int ojj = tid >> 3;
    const int ob  = tid & 7;
    const float g  = gamma[jbase + ojj];
    const float e  = eps[jbase + ojj];
    const float bi = bias[jbase + ojj];
    float hy = 0.0f, hz = 0.0f;

    // mbarrier init (count=1: thread0's arm-arrive; completion needs TX_BYTES)
    const uint32_t bar_local0 = smem_u32(&smem[OFF_BAR]);
    const uint32_t bar_local1 = bar_local0 + 8u;
    if (tid == 0) {
        asm volatile("mbarrier.init.shared.b64 [%0], 1;" :: "r"(bar_local0) : "memory");
        asm volatile("mbarrier.init.shared.b64 [%0], 1;" :: "r"(bar_local1) : "memory");
    }

    // Cluster-mapped smem base of every rank (incl. self)
    uint32_t rem_base[CLUSTER_SZ];
    {
        uint32_t loc = smem_u32(&smem[0]);
        #pragma unroll
        for (int q = 0; q < CLUSTER_SZ; ++q)
            asm("mapa.shared::cluster.u32 %0, %1, %2;" : "=r"(rem_base[q]) : "r"(loc), "r"(q));
    }

    // One-time full cluster sync: barriers init'd + phase-0 mirror/xs visible
    asm volatile("barrier.cluster.arrive.aligned;" ::: "memory");
    asm volatile("barrier.cluster.wait.aligned;"   ::: "memory");

    // Byte offsets (relative to smem base) for per-phase targets
    const uint32_t hy_push_off[2] = {
        (uint32_t)(OFF_HY0 + jbase * 8 + tid) * 4u,
        (uint32_t)(OFF_HY1 + jbase * 8 + tid) * 4u };
    const uint32_t xs_push_off[2] = {
        (uint32_t)(OFF_XS0 + pf_i * 8 + pf_b) * 4u,
        (uint32_t)(OFF_XS1 + pf_i * 8 + pf_b) * 4u };
    const uint32_t bar_off[2] = { (uint32_t)OFF_BAR * 4u, (uint32_t)OFF_BAR * 4u + 8u };
    const uint32_t self_base = rem_base[r];

    // Shared-space base addresses for matvec LDS
    const uint32_t hy0_base = smem_u32(&smem[OFF_HY0]) + (uint32_t)k0 * 32u;
    const uint32_t hy1_base = smem_u32(&smem[OFF_HY1]) + (uint32_t)k0 * 32u;
    const uint32_t xs0_base = smem_u32(&smem[OFF_XS0]) + (uint32_t)i0 * 32u;
    const uint32_t xs1_base = smem_u32(&smem[OFF_XS1]) + (uint32_t)i0 * 32u;

    for (int t = 0; t < Tx; ++t) {
        const int ph  = t & 1;
        const int nph = ph ^ 1;
        const uint32_t hyp_b = ph ? hy1_base : hy0_base;      // read mirror (this warp's k slice)
        const uint32_t xr_b  = ph ? xs1_base : xs0_base;      // x staging (this warp's i slice)

        // Arm next-phase barrier (tx can arrive before/after arming; count is signed)
        if (t + 1 < Tx && tid == 0) {
            asm volatile("mbarrier.arrive.expect_tx.shared.b64 _, [%0], %1;"
                         :: "r"(nph ? bar_local1 : bar_local0), "r"(TX_BYTES) : "memory");
        }

        // Issue next timestep's x load early
        float xnext = 0.0f;
        if (t + 1 < Tx)
            xnext = __ldg(xsrc_base + (size_t)(t + 1) * Ix);

        // ---- Partial matvec: packed f32x2, weights from registers ----
        uint64_t acc[4][2];
        #pragma unroll
        for (int p = 0; p < 4; ++p) { acc[p][0] = 0ull; acc[p][1] = 0ull; }

        #pragma unroll
        for (int kk = 0; kk < 32; ++kk) {
            uint64_t h01, h23, h45, h67;
            uint32_t a = hyp_b + (uint32_t)kk * 32u;
            asm("ld.shared.v2.u64 {%0, %1}, [%2];"      : "=l"(h01), "=l"(h23) : "r"(a));
            asm("ld.shared.v2.u64 {%0, %1}, [%2 + 16];" : "=l"(h45), "=l"(h67) : "r"(a));
            uint64_t wxx = pack2(wreg[kk].x, wreg[kk].x);
            uint64_t wyy = pack2(wreg[kk].y, wreg[kk].y);
            accp16(acc, wxx, wyy, h01, h23, h45, h67);
        }
        // Input projection slice (i-range of this warp), x2h weights from SMEM
        #pragma unroll
        for (int ii = 0; ii < 4; ++ii) {
            float2 w2 = *(const float2*)(smem + OFF_X2H + (i0 + ii) * JPC + jj0);
            uint64_t h01, h23, h45, h67;
            uint32_t a = xr_b + (uint32_t)ii * 32u;
            asm("ld.shared.v2.u64 {%0, %1}, [%2];"      : "=l"(h01), "=l"(h23) : "r"(a));
            asm("ld.shared.v2.u64 {%0, %1}, [%2 + 16];" : "=l"(h45), "=l"(h67) : "r"(a));
            uint64_t wxx = pack2(w2.x, w2.x);
            uint64_t wyy = pack2(w2.y, w2.y);
            accp16(acc, wxx, wyy, h01, h23, h45, h67);
        }

        // ---- Cross-warp reduction: red[w][b*68 + jj] (write conflict-free, pad 68) ----
        {
            float* rw = smem + OFF_RED + w * RSTRIDE;
            #pragma unroll
            for (int p = 0; p < 4; ++p) {
                float j0_b0, j0_b1, j1_b0, j1_b1;
                asm("mov.b64 {%0, %1}, %2;" : "=f"(j0_b0), "=f"(j0_b1) : "l"(acc[p][0]));
                asm("mov.b64 {%0, %1}, %2;" : "=f"(j1_b0), "=f"(j1_b1) : "l"(acc[p][1]));
                *(float2*)(rw + (2 * p)     * 68 + jj0) = make_float2(j0_b0, j1_b0);
                *(float2*)(rw + (2 * p + 1) * 68 + jj0) = make_float2(j0_b1, j1_b1);
            }
        }
        __syncthreads();

        float u = bi;
        {
            const float* rp = smem + OFF_RED + ob * 68 + ojj;
            #pragma unroll
            for (int ww = 0; ww < 16; ++ww)
                u += rp[ww * RSTRIDE];
        }

        // ---- Oscillator update ----
        float v;
        asm("tanh.approx.f32 %0, %1;" : "=f"(v) : "f"(u));
        hz += RON_DT * (v - g * hy - e * hz);
        hy += RON_DT * hz;

        if (t + 1 < Tx) {
            // Push hy to all 8 ranks' next-phase mirror (coalesced 128B/warp/rank)
            const uint32_t moff = hy_push_off[nph];
            const uint32_t boff = bar_off[nph];
            #pragma unroll
            for (int q = 0; q < CLUSTER_SZ; ++q)
                st_async_f32(rem_base[q] + moff, hy, rem_base[q] + boff);
            // Stage next x into own next-phase staging (counts toward own barrier)
            st_async_f32(self_base + xs_push_off[nph], xnext, self_base + boff);

            // Overlap the states STG with peers' pushes
            out_states[(size_t)(b0 + ob) * Tx * Hx + (size_t)t * Hx + jbase + ojj] = hy;

            // Wait for next-phase data (parity = (t>>1)&1 for both barriers)
            {
                const uint32_t bar = nph ? bar_local1 : bar_local0;
                const uint32_t parity = (uint32_t)(t >> 1) & 1u;
                uint32_t done;
                asm volatile(
                    "{\n\t.reg .pred p;\n\t"
                    "mbarrier.try_wait.parity.acquire.cta.shared::cta.b64 p, [%1], %2;\n\t"
                    "selp.b32 %0, 1, 0, p;\n\t}"
                    : "=r"(done) : "r"(bar), "r"(parity) : "memory");
                if (!done) {
                    asm volatile(
                        "{\n\t.reg .pred P1;\n\t"
                        "WAIT_LOOP_%=:\n\t"
                        "mbarrier.try_wait.parity.acquire.cta.shared::cta.b64 P1, [%0], %1, 0x989680;\n\t"
                        "@P1 bra.uni WAIT_DONE_%=;\n\t"
                        "bra.uni WAIT_LOOP_%=;\n\t"
                        "WAIT_DONE_%=:\n\t}"
                        :: "r"(bar), "r"(parity) : "memory");
                }
            }
        } else {
            out_states[(size_t)(b0 + ob) * Tx * Hx + (size_t)t * Hx + jbase + ojj] = hy;
        }
    }

    if (write_hy)
        out_hy[(size_t)(b0 + ob) * Hx + jbase + ojj] = hy;

    // Keep CTAs resident until all in-flight remote stores are consumed
    asm volatile("barrier.cluster.arrive.aligned;" ::: "memory");
    asm volatile("barrier.cluster.wait.aligned;"   ::: "memory");
}

extern "C" void kernel_launch(void* const* d_in, const int* in_sizes, int n_in,
                              void* d_out, int out_size) {
    const float* x     = (const float*)d_in[0];
    const float* x2h   = (const float*)d_in[1];
    const float* h2h   = (const float*)d_in[2];
    const float* bias  = (const float*)d_in[3];
    const float* gamma = (const float*)d_in[4];
    const float* eps   = (const float*)d_in[5];

    float* out_states = (float*)d_out;
    const size_t states_elems = (size_t)Bx * Tx * Hx;
    int write_hy = (out_size >= (int)(states_elems + (size_t)Bx * Hx)) ? 1 : 0;
    float* out_hy = out_states + states_elems;

    cudaFuncSetAttribute(ron_cluster_kernel,
                         cudaFuncAttributeMaxDynamicSharedMemorySize, (int)SMEM_BYTES);

    ron_cluster_kernel<<<dim3(Bx), dim3(NTHREADS), SMEM_BYTES>>>(
        x, x2h, h2h, bias, gamma, eps, out_states, out_hy, write_hy);
}

// round 12
// speedup vs baseline: 1.1419x; 1.1419x over previous
#include <cuda_runtime.h>
#include <cstdint>
#include <cstddef>

// Problem constants (fixed shapes for this bench)
#define RON_DT 0.042f
static constexpr int Bx = 128;   // batch
static constexpr int Tx = 1024;  // timesteps
static constexpr int Ix = 64;    // input dim
static constexpr int Hx = 512;   // hidden dim
static constexpr int NTHREADS = 512;

// Cluster partitioning: 16 clusters x 8 CTAs. Each cluster owns 8 batches,
// each CTA owns 64 j-columns. h2h weights live in REGISTERS (64/thread).
// Exchange: plain st.shared::cluster direct from registers (coalesced),
// one cluster barrier + one __syncthreads per step.
static constexpr int CLUSTER_SZ = 8;
static constexpr int JPC = 64;   // j columns per CTA
static constexpr int BPC = 8;    // batches per cluster

// SMEM layout (float offsets)
static constexpr int OFF_X2H = 0;          // [64][64]   x2h column slice
static constexpr int OFF_HY0 = 4096;       // [512][8]   hy mirror, phase 0 (k-major, b fastest)
static constexpr int OFF_HY1 = 8192;       // [512][8]   hy mirror, phase 1
static constexpr int OFF_XS0 = 12288;      // [64][8]    x staging, phase 0
static constexpr int OFF_XS1 = 12800;      // [64][8]    x staging, phase 1
static constexpr int OFF_RED = 13312;      // [16][8*68] cross-warp reduction (pad 68)
static constexpr int RSTRIDE = 8 * 68;     // 544 floats per warp row
static constexpr int SMEM_FLOATS = OFF_RED + 16 * RSTRIDE;  // 22016
static constexpr size_t SMEM_BYTES = (size_t)SMEM_FLOATS * 4;  // 88064 B

__device__ __forceinline__ uint32_t smem_u32(const void* p) {
    return (uint32_t)__cvta_generic_to_shared(p);
}

__device__ __forceinline__ uint64_t pack2(float lo, float hi) {
    uint64_t d;
    asm("mov.b64 %0, {%1, %2};" : "=l"(d) : "f"(lo), "f"(hi));
    return d;
}

__device__ __forceinline__ uint64_t fma2(uint64_t a, uint64_t b, uint64_t c) {
    uint64_t d;
    asm("fma.rn.f32x2 %0, %1, %2, %3;" : "=l"(d) : "l"(a), "l"(b), "l"(c));
    return d;
}

// 8 packed FMA2 = 16 scalar FMAs: batch-pairs h01..h67 x packed-splat weights wxx/wyy
__device__ __forceinline__ void accp16(uint64_t (&acc)[4][2], uint64_t wxx, uint64_t wyy,
                                       uint64_t h01, uint64_t h23, uint64_t h45, uint64_t h67) {
    acc[0][0] = fma2(h01, wxx, acc[0][0]); acc[0][1] = fma2(h01, wyy, acc[0][1]);
    acc[1][0] = fma2(h23, wxx, acc[1][0]); acc[1][1] = fma2(h23, wyy, acc[1][1]);
    acc[2][0] = fma2(h45, wxx, acc[2][0]); acc[2][1] = fma2(h45, wyy, acc[2][1]);
    acc[3][0] = fma2(h67, wxx, acc[3][0]); acc[3][1] = fma2(h67, wyy, acc[3][1]);
}

extern __shared__ float smem[];

__global__ void __cluster_dims__(CLUSTER_SZ, 1, 1) __launch_bounds__(NTHREADS, 1)
ron_cluster_kernel(const float* __restrict__ x,
                   const float* __restrict__ x2h,
                   const float* __restrict__ h2h,
                   const float* __restrict__ bias,
                   const float* __restrict__ gamma,
                   const float* __restrict__ eps,
                   float* __restrict__ out_states,
                   float* __restrict__ out_hy,
                   int write_hy)
{
    const int tid  = threadIdx.x;
    const int w    = tid >> 5;     // warp 0..15 -> k-slice
    const int lane = tid & 31;

    uint32_t rank_u;
    asm("mov.u32 %0, %%cluster_ctarank;" : "=r"(rank_u));
    const int r     = (int)rank_u;            // j-slice owner within cluster
    const int cl    = blockIdx.x >> 3;        // cluster id
    const int b0    = cl * BPC;               // first global batch of this cluster
    const int jbase = r * JPC;                // first global j of this CTA

    const int k0  = w * 32;    // this warp's k slice (recurrent matvec)
    const int i0  = w * 4;     // this warp's i slice (input projection)
    const int jj0 = lane * 2;  // this lane's j pair

    // ---- Prologue ----
    // h2h weights into REGISTERS: thread holds w[kk] = (h2h[k0+kk][jbase+jj0], ...+1)
    float2 wreg[32];
    {
        const float2* src = reinterpret_cast<const float2*>(h2h + (size_t)k0 * Hx + jbase + jj0);
        #pragma unroll
        for (int kk = 0; kk < 32; ++kk)
            wreg[kk] = __ldg(src + (size_t)kk * (Hx / 2));
    }
    // x2h slice into SMEM: [64][64]
    #pragma unroll
    for (int it = 0; it < (Ix * JPC) / NTHREADS; ++it) {
        int idx = it * NTHREADS + tid;
        int i = idx >> 6, jj = idx & 63;
        smem[OFF_X2H + idx] = x2h[(size_t)i * Hx + jbase + jj];
    }
    // zero hy mirror phase 0 (initial hidden state)
    #pragma unroll
    for (int it = 0; it < (Hx * BPC) / NTHREADS; ++it)
        smem[OFF_HY0 + it * NTHREADS + tid] = 0.0f;

    // stage x for t=0 into xs phase 0: layout xs[i][b]
    const int pf_b = tid >> 6, pf_i = tid & 63;
    const float* xsrc_base = x + (size_t)(b0 + pf_b) * Tx * Ix + pf_i;
    smem[OFF_XS0 + pf_i * 8 + pf_b] = xsrc_base[0];

    // Update ownership: thread tid owns (column ojj = tid>>3, batch ob = tid&7)
    // so the mirror offset (jbase+ojj)*8+ob == jbase*8 + tid (lane-consecutive).
    const int ojj = tid >> 3;
    const int ob  = tid & 7;
    const float g  = gamma[jbase + ojj];
    const float e  = eps[jbase + ojj];
    const float bi = bias[jbase + ojj];
    float hy = 0.0f, hz = 0.0f;

    // Cluster-mapped smem base of the 7 peer ranks
    uint32_t peer_base[CLUSTER_SZ - 1];
    {
        uint32_t loc = smem_u32(&smem[0]);
        #pragma unroll
        for (int q = 0; q < CLUSTER_SZ - 1; ++q) {
            int pr = (r + 1 + q) & 7;
            asm("mapa.shared::cluster.u32 %0, %1, %2;" : "=r"(peer_base[q]) : "r"(loc), "r"(pr));
        }
    }
    // Per-phase byte offsets of this thread's mirror slot
    const uint32_t hy_off[2] = {
        (uint32_t)(OFF_HY0 + jbase * 8 + tid) * 4u,
        (uint32_t)(OFF_HY1 + jbase * 8 + tid) * 4u };

    // Prologue done everywhere before first step (also CTA-internal sync)
    asm volatile("barrier.cluster.arrive.aligned;" ::: "memory");
    asm volatile("barrier.cluster.wait.aligned;"   ::: "memory");

    // Shared-space base addresses for matvec LDS
    const uint32_t hy0_base = smem_u32(&smem[OFF_HY0]) + (uint32_t)k0 * 32u;
    const uint32_t hy1_base = smem_u32(&smem[OFF_HY1]) + (uint32_t)k0 * 32u;
    const uint32_t xs0_base = smem_u32(&smem[OFF_XS0]) + (uint32_t)i0 * 32u;
    const uint32_t xs1_base = smem_u32(&smem[OFF_XS1]) + (uint32_t)i0 * 32u;
    float* const mir[2] = { smem + OFF_HY0, smem + OFF_HY1 };

    for (int t = 0; t < Tx; ++t) {
        const int ph  = t & 1;
        const int nph = ph ^ 1;
        const uint32_t hyp_b = ph ? hy1_base : hy0_base;      // read mirror (this warp's k slice)
        const uint32_t xr_b  = ph ? xs1_base : xs0_base;      // x staging (this warp's i slice)
        float* xw = smem + (ph ? OFF_XS0 : OFF_XS1);

        // Issue next timestep's x load early; STS happens at end of step.
        float xnext = 0.0f;
        if (t + 1 < Tx)
            xnext = __ldg(xsrc_base + (size_t)(t + 1) * Ix);

        // ---- Partial matvec: packed f32x2, weights from registers ----
        uint64_t acc[4][2];
        #pragma unroll
        for (int p = 0; p < 4; ++p) { acc[p][0] = 0ull; acc[p][1] = 0ull; }

        #pragma unroll
        for (int kk = 0; kk < 32; ++kk) {
            uint64_t h01, h23, h45, h67;
            uint32_t a = hyp_b + (uint32_t)kk * 32u;
            asm("ld.shared.v2.u64 {%0, %1}, [%2];"      : "=l"(h01), "=l"(h23) : "r"(a));
            asm("ld.shared.v2.u64 {%0, %1}, [%2 + 16];" : "=l"(h45), "=l"(h67) : "r"(a));
            uint64_t wxx = pack2(wreg[kk].x, wreg[kk].x);
            uint64_t wyy = pack2(wreg[kk].y, wreg[kk].y);
            accp16(acc, wxx, wyy, h01, h23, h45, h67);
        }
        // Input projection slice (i-range of this warp), x2h weights from SMEM
        #pragma unroll
        for (int ii = 0; ii < 4; ++ii) {
            float2 w2 = *(const float2*)(smem + OFF_X2H + (i0 + ii) * JPC + jj0);
            uint64_t h01, h23, h45, h67;
            uint32_t a = xr_b + (uint32_t)ii * 32u;
            asm("ld.shared.v2.u64 {%0, %1}, [%2];"      : "=l"(h01), "=l"(h23) : "r"(a));
            asm("ld.shared.v2.u64 {%0, %1}, [%2 + 16];" : "=l"(h45), "=l"(h67) : "r"(a));
            uint64_t wxx = pack2(w2.x, w2.x);
            uint64_t wyy = pack2(w2.y, w2.y);
            accp16(acc, wxx, wyy, h01, h23, h45, h67);
        }

        // ---- Cross-warp reduction: red[w][b*68 + jj] (conflict-free, pad 68) ----
        {
            float* rw = smem + OFF_RED + w * RSTRIDE;
            #pragma unroll
            for (int p = 0; p < 4; ++p) {
                float j0_b0, j0_b1, j1_b0, j1_b1;
                asm("mov.b64 {%0, %1}, %2;" : "=f"(j0_b0), "=f"(j0_b1) : "l"(acc[p][0]));
                asm("mov.b64 {%0, %1}, %2;" : "=f"(j1_b0), "=f"(j1_b1) : "l"(acc[p][1]));
                *(float2*)(rw + (2 * p)     * 68 + jj0) = make_float2(j0_b0, j1_b0);
                *(float2*)(rw + (2 * p + 1) * 68 + jj0) = make_float2(j0_b1, j1_b1);
            }
        }
        __syncthreads();

        // Balanced-tree sum of 16 partials (read banks 4*b+a: conflict-free)
        float u;
        {
            const float* rp = smem + OFF_RED + ob * 68 + ojj;
            float s[16];
            #pragma unroll
            for (int ww = 0; ww < 16; ++ww) s[ww] = rp[ww * RSTRIDE];
            #pragma unroll
            for (int d = 8; d >= 1; d >>= 1)
                #pragma unroll
                for (int i2 = 0; i2 < d; ++i2) s[i2] += s[i2 + d];
            u = bi + s[0];
        }

        // ---- Oscillator update ----
        float v;
        asm("tanh.approx.f32 %0, %1;" : "=f"(v) : "f"(u));
        hz += RON_DT * (v - g * hy - e * hz);
        hy += RON_DT * hz;

        // ---- Push hy: own next-phase mirror (coalesced local) + 7 peers ----
        mir[nph][jbase * 8 + tid] = hy;
        {
            const uint32_t moff = hy_off[nph];
            #pragma unroll
            for (int q = 0; q < CLUSTER_SZ - 1; ++q)
                asm volatile("st.shared::cluster.f32 [%0], %1;"
                             :: "r"(peer_base[q] + moff), "f"(hy) : "memory");
        }

        // Stage prefetched x for next step (xw is not read by anyone this step)
        if (t + 1 < Tx)
            xw[pf_i * 8 + pf_b] = xnext;

        // Release pushes; overlap the out_states STG with peers' arrival
        asm volatile("barrier.cluster.arrive.aligned;" ::: "memory");

        out_states[(size_t)(b0 + ob) * Tx * Hx + (size_t)t * Hx + jbase + ojj] = hy;

        asm volatile("barrier.cluster.wait.aligned;" ::: "memory");
    }

    if (write_hy)
        out_hy[(size_t)(b0 + ob) * Hx + jbase + ojj] = hy;
}

extern "C" void kernel_launch(void* const* d_in, const int* in_sizes, int n_in,
                              void* d_out, int out_size) {
    const float* x     = (const float*)d_in[0];
    const float* x2h   = (const float*)d_in[1];
    const float* h2h   = (const float*)d_in[2];
    const float* bias  = (const float*)d_in[3];
    const float* gamma = (const float*)d_in[4];
    const float* eps   = (const float*)d_in[5];

    float* out_states = (float*)d_out;
    const size_t states_elems = (size_t)Bx * Tx * Hx;
    int write_hy = (out_size >= (int)(states_elems + (size_t)Bx * Hx)) ? 1 : 0;
    float* out_hy = out_states + states_elems;

    cudaFuncSetAttribute(ron_cluster_kernel,
                         cudaFuncAttributeMaxDynamicSharedMemorySize, (int)SMEM_BYTES);

    ron_cluster_kernel<<<dim3(Bx), dim3(NTHREADS), SMEM_BYTES>>>(
        x, x2h, h2h, bias, gamma, eps, out_states, out_hy, write_hy);
}

// round 16
// speedup vs baseline: 1.5093x; 1.3218x over previous
#include <cuda_runtime.h>
#include <cstdint>
#include <cstddef>

// Problem constants (fixed shapes for this bench)
#define RON_DT 0.042f
static constexpr int Bx = 128;   // batch
static constexpr int Tx = 1024;  // timesteps
static constexpr int Ix = 64;    // input dim
static constexpr int Hx = 512;   // hidden dim
static constexpr int NTHREADS = 512;

// 32 clusters x 8 CTAs = 256 CTAs (2 per SM). Each cluster owns 4 batches,
// each CTA owns 64 j-columns. h2h weights live in registers as bf16x2
// (32 regs/thread), expanded to fp32 per use; accumulation is fp32.
static constexpr int CLUSTER_SZ = 8;
static constexpr int JPC = 64;   // j columns per CTA
static constexpr int BPC = 4;    // batches per cluster

// SMEM layout (float offsets)
static constexpr int OFF_X2H = 0;          // [64][64]   x2h column slice (fp32)
static constexpr int OFF_HY0 = 4096;       // [512][4]   hy mirror, phase 0 (k-major, b fastest)
static constexpr int OFF_HY1 = 6144;       // [512][4]   hy mirror, phase 1
static constexpr int OFF_XS0 = 8192;       // [64][4]    x staging, phase 0
static constexpr int OFF_XS1 = 8448;       // [64][4]    x staging, phase 1
static constexpr int OFF_RED = 8704;       // [16][4*68] cross-warp reduction (pad 68)
static constexpr int RSTRIDE = 4 * 68;     // 272 floats per warp row
static constexpr int SMEM_FLOATS = OFF_RED + 16 * RSTRIDE;  // 13056
static constexpr size_t SMEM_BYTES = (size_t)SMEM_FLOATS * 4;  // 52224 B (x2 fits an SM)

__device__ __forceinline__ uint32_t smem_u32(const void* p) {
    return (uint32_t)__cvta_generic_to_shared(p);
}

extern __shared__ float smem[];

__global__ void __cluster_dims__(CLUSTER_SZ, 1, 1) __launch_bounds__(NTHREADS, 2)
ron_cluster_kernel(const float* __restrict__ x,
                   const float* __restrict__ x2h,
                   const float* __restrict__ h2h,
                   const float* __restrict__ bias,
                   const float* __restrict__ gamma,
                   const float* __restrict__ eps,
                   float* __restrict__ out_states,
                   float* __restrict__ out_hy,
                   int write_hy)
{
    const int tid  = threadIdx.x;
    const int w    = tid >> 5;     // warp 0..15 -> k-slice
    const int lane = tid & 31;

    uint32_t rank_u;
    asm("mov.u32 %0, %%cluster_ctarank;" : "=r"(rank_u));
    const int r     = (int)rank_u;            // j-slice owner within cluster
    const int cl    = blockIdx.x >> 3;        // cluster id (0..31)
    const int b0    = cl * BPC;               // first global batch of this cluster
    const int jbase = r * JPC;                // first global j of this CTA

    const int k0  = w * 32;    // this warp's k slice (recurrent matvec)
    const int i0  = w * 4;     // this warp's i slice (input projection)
    const int jj0 = lane * 2;  // this lane's j pair

    // ---- Prologue ----
    // h2h weights into REGISTERS as bf16x2: wbf[kk] = (bf16(w[k][j0]), bf16(w[k][j1]))
    uint32_t wbf[32];
    {
        const float2* src = reinterpret_cast<const float2*>(h2h + (size_t)k0 * Hx + jbase + jj0);
        #pragma unroll
        for (int kk = 0; kk < 32; ++kk) {
            float2 wp = __ldg(src + (size_t)kk * (Hx / 2));
            // hi = wp.y (j1), lo = wp.x (j0), round-to-nearest
            asm("cvt.rn.bf16x2.f32 %0, %1, %2;" : "=r"(wbf[kk]) : "f"(wp.y), "f"(wp.x));
        }
    }
    // x2h slice into SMEM (fp32): [64][64]
    #pragma unroll
    for (int it = 0; it < (Ix * JPC) / NTHREADS; ++it) {
        int idx = it * NTHREADS + tid;
        int i = idx >> 6, jj = idx & 63;
        smem[OFF_X2H + idx] = x2h[(size_t)i * Hx + jbase + jj];
    }
    // zero hy mirror phase 0 (initial hidden state): 2048 floats
    #pragma unroll
    for (int it = 0; it < (Hx * BPC) / NTHREADS; ++it)
        smem[OFF_HY0 + it * NTHREADS + tid] = 0.0f;

    // x prefetch slots: threads 0..255 own (pf_i, pf_b)
    const int pf_b = (tid >> 6) & 3;
    const int pf_i = tid & 63;
    const float* xsrc_base = x + (size_t)(b0 + pf_b) * Tx * Ix + pf_i;
    if (tid < 256)
        smem[OFF_XS0 + pf_i * 4 + pf_b] = xsrc_base[0];

    // Update ownership (threads 0..255): thread owns (ojj = tid&63, ob = tid>>6)
    const int ojj = tid & 63;
    const int ob  = (tid >> 6) & 3;
    float g = 0.f, e = 0.f, bi = 0.f;
    if (tid < 256) {
        g  = gamma[jbase + ojj];
        e  = eps[jbase + ojj];
        bi = bias[jbase + ojj];
    }
    float hy = 0.0f, hz = 0.0f;

    // Push assignment: warps 0..13 copy the CTA's 256-float slab to the 7 peers
    // (2 warps per peer, 128 floats each: 4 coalesced 32-float warp-stores).
    const int push_peer = (r + 1 + (w >> 1)) & 7;            // peers r+1..r+7
    const int push_off  = jbase * 4 + (w & 1) * 128 + lane;  // float offset of first element

    uint32_t pushA = 0, pushB = 0;
    {
        uint32_t locA = smem_u32(&smem[OFF_HY0 + push_off]);
        uint32_t locB = smem_u32(&smem[OFF_HY1 + push_off]);
        asm("mapa.shared::cluster.u32 %0, %1, %2;" : "=r"(pushA) : "r"(locA), "r"(push_peer));
        asm("mapa.shared::cluster.u32 %0, %1, %2;" : "=r"(pushB) : "r"(locB), "r"(push_peer));
    }

    // Prologue done everywhere before first step
    asm volatile("barrier.cluster.arrive.aligned;" ::: "memory");
    asm volatile("barrier.cluster.wait.aligned;"   ::: "memory");

    // Base addresses for matvec LDS (this warp's k slice / i slice); rows are 16B
    const float* hyp0 = smem + OFF_HY0 + k0 * 4;
    const float* hyp1 = smem + OFF_HY1 + k0 * 4;
    const float* xsr0 = smem + OFF_XS0 + i0 * 4;
    const float* xsr1 = smem + OFF_XS1 + i0 * 4;
    float* const mir0 = smem + OFF_HY0;
    float* const mir1 = smem + OFF_HY1;

    for (int t = 0; t < Tx; ++t) {
        const int ph = t & 1;
        const float* hyp = ph ? hyp1 : hyp0;    // read mirror (warp's k slice)
        const float* xr  = ph ? xsr1 : xsr0;    // x staging (warp's i slice)
        float* wmir = ph ? mir0 : mir1;         // write mirror (next phase)
        float* xw   = smem + (ph ? OFF_XS0 : OFF_XS1);

        // Issue next timestep's x load early; STS happens at end of step.
        float xnext = 0.0f;
        if (tid < 256 && t + 1 < Tx)
            xnext = __ldg(xsrc_base + (size_t)(t + 1) * Ix);

        // ---- Partial matvec: 2 j x 4 b per lane, fp32 accum, bf16 weights ----
        float a00 = 0.f, a01 = 0.f, a10 = 0.f, a11 = 0.f;   // b0,b1 x j0,j1
        float a20 = 0.f, a21 = 0.f, a30 = 0.f, a31 = 0.f;   // b2,b3 x j0,j1

        #pragma unroll
        for (int kk = 0; kk < 32; ++kk) {
            float4 h = *(const float4*)(hyp + kk * 4);      // hy[k][0..3], broadcast
            uint32_t wb = wbf[kk];
            float w0 = __uint_as_float(wb << 16);           // bf16 lo -> fp32 (j0)
            float w1 = __uint_as_float(wb & 0xffff0000u);   // bf16 hi -> fp32 (j1)
            a00 = fmaf(h.x, w0, a00); a01 = fmaf(h.x, w1, a01);
            a10 = fmaf(h.y, w0, a10); a11 = fmaf(h.y, w1, a11);
            a20 = fmaf(h.z, w0, a20); a21 = fmaf(h.z, w1, a21);
            a30 = fmaf(h.w, w0, a30); a31 = fmaf(h.w, w1, a31);
        }
        // Input projection: this warp's 4 i-rows, x2h fp32 from SMEM
        #pragma unroll
        for (int ii = 0; ii < 4; ++ii) {
            float2 w2 = *(const float2*)(smem + OFF_X2H + (i0 + ii) * JPC + jj0);
            float4 h  = *(const float4*)(xr + ii * 4);      // x[i][0..3], broadcast
            a00 = fmaf(h.x, w2.x, a00); a01 = fmaf(h.x, w2.y, a01);
            a10 = fmaf(h.y, w2.x, a10); a11 = fmaf(h.y, w2.y, a11);
            a20 = fmaf(h.z, w2.x, a20); a21 = fmaf(h.z, w2.y, a21);
            a30 = fmaf(h.w, w2.x, a30); a31 = fmaf(h.w, w2.y, a31);
        }

        // ---- Cross-warp reduction: red[w][b*68 + jj] (conflict-free, pad 68) ----
        {
            float* rw = smem + OFF_RED + w * RSTRIDE + jj0;
            *(float2*)(rw + 0 * 68) = make_float2(a00, a01);
            *(float2*)(rw + 1 * 68) = make_float2(a10, a11);
            *(float2*)(rw + 2 * 68) = make_float2(a20, a21);
            *(float2*)(rw + 3 * 68) = make_float2(a30, a31);
        }
        __syncthreads();

        if (tid < 256) {
            // Sum 16 warp rows (every warp covers every j). Banks (4*ob+ojj)%32
            // distinct within a warp: conflict-free.
            const float* rp = smem + OFF_RED + ob * 68 + ojj;
            float s0 = rp[0 * RSTRIDE],  s1 = rp[1 * RSTRIDE];
            float s2 = rp[2 * RSTRIDE],  s3 = rp[3 * RSTRIDE];
            s0 += rp[4 * RSTRIDE];  s1 += rp[5 * RSTRIDE];
            s2 += rp[6 * RSTRIDE];  s3 += rp[7 * RSTRIDE];
            s0 += rp[8 * RSTRIDE];  s1 += rp[9 * RSTRIDE];
            s2 += rp[10 * RSTRIDE]; s3 += rp[11 * RSTRIDE];
            s0 += rp[12 * RSTRIDE]; s1 += rp[13 * RSTRIDE];
            s2 += rp[14 * RSTRIDE]; s3 += rp[15 * RSTRIDE];
            float u = bi + ((s0 + s1) + (s2 + s3));

            // ---- Oscillator update ----
            float v;
            asm("tanh.approx.f32 %0, %1;" : "=f"(v) : "f"(u));
            hz += RON_DT * (v - g * hy - e * hz);
            hy += RON_DT * hz;

            // Store hy once into OWN next-phase mirror slab
            wmir[(jbase + ojj) * 4 + ob] = hy;
        }
        __syncthreads();   // slab complete; all reads of hyp/red done

        // ---- Bulk-push own slab to the 7 peers: coalesced scalar remote stores ----
        if (w < 14) {
            const float* src = wmir + push_off;
            const uint32_t dstb = ph ? pushA : pushB;   // next-phase mirror in peer
            #pragma unroll
            for (int it = 0; it < 4; ++it) {
                float val = src[it * 32];
                asm volatile("st.shared::cluster.f32 [%0], %1;"
                             :: "r"(dstb + (uint32_t)(it * 32 * 4)), "f"(val) : "memory");
            }
        }

        // Stage prefetched x for next step (xw is not read by anyone this step)
        if (tid < 256 && t + 1 < Tx)
            xw[pf_i * 4 + pf_b] = xnext;

        // Release pushes; overlap the out_states STG with peers' arrival
        asm volatile("barrier.cluster.arrive.aligned;" ::: "memory");

        if (tid < 256)
            out_states[(size_t)(b0 + ob) * Tx * Hx + (size_t)t * Hx + jbase + ojj] = hy;

        asm volatile("barrier.cluster.wait.aligned;" ::: "memory");
    }

    if (write_hy && tid < 256)
        out_hy[(size_t)(b0 + ob) * Hx + jbase + ojj] = hy;
}

extern "C" void kernel_launch(void* const* d_in, const int* in_sizes, int n_in,
                              void* d_out, int out_size) {
    const float* x     = (const float*)d_in[0];
    const float* x2h   = (const float*)d_in[1];
    const float* h2h   = (const float*)d_in[2];
    const float* bias  = (const float*)d_in[3];
    const float* gamma = (const float*)d_in[4];
    const float* eps   = (const float*)d_in[5];

    float* out_states = (float*)d_out;
    const size_t states_elems = (size_t)Bx * Tx * Hx;
    int write_hy = (out_size >= (int)(states_elems + (size_t)Bx * Hx)) ? 1 : 0;
    float* out_hy = out_states + states_elems;

    cudaFuncSetAttribute(ron_cluster_kernel,
                         cudaFuncAttributeMaxDynamicSharedMemorySize, (int)SMEM_BYTES);

    // 32 clusters x 8 CTAs = 256 CTAs of 512 threads -> 2 co-resident
    // clusters per SM; one cluster's barrier wait overlaps the other's compute.
    ron_cluster_kernel<<<dim3(2 * Bx), dim3(NTHREADS), SMEM_BYTES>>>(
        x, x2h, h2h, bias, gamma, eps, out_states, out_hy, write_hy);
}